// round 8
// baseline (speedup 1.0000x reference)
#include <cuda_runtime.h>
#include <cstdint>

// PolarToCartesianGrid: batched scatter-add into a cartesian voxel grid.
//
// R8: fork/join graph pipeline (proven mechanism, R5/R6) with 4-batch scatter
// groups and packed per-cell structure.
//   stream 0 : pack kernel (idx[23b]|flags[6b] -> u32, once), then 16
//              per-slab engine memsets, event after each.
//   stream s2: one scatter kernel per 4 batches, gated on the 4th slab's
//              memset event. Packed load amortized x4 (L2-resident after the
//              first group); 4 polar loads issued up front (MLP); the 4
//              warp-segmented reductions interleaved; leader does 4 REDs.
//   join back to stream 0. No device-side spinning anywhere (R7 lesson).

#define NTHR 256
#define MAX_CELLS (1 << 21)
#define MAX_BATCHES 32
#define GROUP 4

__device__ unsigned g_packed[MAX_CELLS];   // idx | (flags<<23)

// flags: bit0 = segment head; bit{1..5} = lane+d (d=1,2,4,8,16) same index
__global__ void pack_kernel(const int* __restrict__ vidx, int n_cells)
{
    const int cell = blockIdx.x * blockDim.x + threadIdx.x;
    if (cell >= n_cells) return;
    const unsigned FULL = 0xFFFFFFFFu;
    const int lane = threadIdx.x & 31;

    const int idx = vidx[cell];
    const int prev = __shfl_up_sync(FULL, idx, 1);
    unsigned f = (lane == 0 || prev != idx) ? 1u : 0u;
    int t;
    t = __shfl_down_sync(FULL, idx, 1);  if (lane + 1  < 32 && t == idx) f |= 2u;
    t = __shfl_down_sync(FULL, idx, 2);  if (lane + 2  < 32 && t == idx) f |= 4u;
    t = __shfl_down_sync(FULL, idx, 4);  if (lane + 4  < 32 && t == idx) f |= 8u;
    t = __shfl_down_sync(FULL, idx, 8);  if (lane + 8  < 32 && t == idx) f |= 16u;
    t = __shfl_down_sync(FULL, idx, 16); if (lane + 16 < 32 && t == idx) f |= 32u;
    g_packed[cell] = (unsigned)idx | (f << 23);
}

// scatter a group of `nb` (1..4) consecutive batches
__global__ __launch_bounds__(NTHR)
void scatter_group_kernel(const float* __restrict__ polar_g,  // batch b0
                          float*       __restrict__ out_g,    // slab b0
                          int n_cells, long long n_vox, int nb)
{
    const int cell = blockIdx.x * blockDim.x + threadIdx.x;
    if (cell >= n_cells) return;               // n_cells % 256 == 0
    const unsigned FULL = 0xFFFFFFFFu;

    const unsigned p   = g_packed[cell];
    const unsigned idx = p & 0x7FFFFFu;
    const unsigned f   = p >> 23;

    // all polar loads up front (MLP 4)
    float v[GROUP];
    #pragma unroll
    for (int i = 0; i < GROUP; ++i)
        v[i] = (i < nb) ? __ldg(polar_g + (size_t)i * n_cells + cell) : 0.f;

    // interleaved segmented suffix reductions (head lane ends with run sum)
    float t[GROUP];
    #pragma unroll
    for (int d = 1; d <= 16; d <<= 1) {
        #pragma unroll
        for (int i = 0; i < GROUP; ++i) t[i] = __shfl_down_sync(FULL, v[i], d);
        const unsigned bit = (unsigned)d << 1;      // d=1->2, 2->4, ... 16->32
        if (f & bit) {
            #pragma unroll
            for (int i = 0; i < GROUP; ++i) v[i] += t[i];
        }
    }

    if (f & 1u) {
        #pragma unroll
        for (int i = 0; i < GROUP; ++i)
            if (i < nb) atomicAdd(out_g + (long long)i * n_vox + idx, v[i]);
    }
}

// fallback: R1-style serial path (no packing/stream assumptions)
__global__ void scatter_fallback_kernel(const float* __restrict__ polar_b,
                                        const int*   __restrict__ vidx,
                                        float*       __restrict__ out_b,
                                        int n_cells)
{
    const int cell = blockIdx.x * blockDim.x + threadIdx.x;
    if (cell >= n_cells) return;
    const unsigned FULL = 0xFFFFFFFFu;
    const int lane = threadIdx.x & 31;
    const int idx = vidx[cell];
    float v = __ldg(polar_b + cell);
    const unsigned peers = __match_any_sync(FULL, idx);
    const int rank = __popc(peers & ((1u << lane) - 1u));
    const unsigned s1  = __fns(peers, lane, 2);
    const unsigned s2  = __fns(peers, lane, 3);
    const unsigned s4  = __fns(peers, lane, 5);
    const unsigned s8  = __fns(peers, lane, 9);
    const unsigned s16 = __fns(peers, lane, 17);
    float t;
    t = __shfl_sync(FULL, v, s1  & 31); if (s1  < 32) v += t;
    t = __shfl_sync(FULL, v, s2  & 31); if (s2  < 32) v += t;
    t = __shfl_sync(FULL, v, s4  & 31); if (s4  < 32) v += t;
    t = __shfl_sync(FULL, v, s8  & 31); if (s8  < 32) v += t;
    t = __shfl_sync(FULL, v, s16 & 31); if (s16 < 32) v += t;
    if (rank == 0) atomicAdd(out_b + idx, v);
}

extern "C" void kernel_launch(void* const* d_in, const int* in_sizes, int n_in,
                              void* d_out, int out_size)
{
    const float* polar = (const float*)d_in[0];            // [B,1,El,R,Az] f32
    const int*   vidx  = (const int*)d_in[1];              // [El*R*Az] int32
    float*       out   = (float*)d_out;                    // [B,1,Z,Y,X] f32

    const int n_cells = in_sizes[1];                       // 1,048,576
    int batches = in_sizes[0] / n_cells;                   // 16
    if (batches > MAX_BATCHES) batches = MAX_BATCHES;
    const long long n_vox = (long long)out_size / batches; // 8,192,000

    const int blocks = (n_cells + NTHR - 1) / NTHR;
    const bool packable = (n_cells <= MAX_CELLS) && (n_vox < (1LL << 23));

    cudaStream_t s2 = nullptr;
    cudaEvent_t  evZ[MAX_BATCHES] = {};
    cudaEvent_t  evJoin = nullptr;
    bool multi = packable &&
                 (cudaStreamCreateWithFlags(&s2, cudaStreamNonBlocking) == cudaSuccess);
    for (int i = 0; i < batches && multi; ++i)
        multi = (cudaEventCreateWithFlags(&evZ[i], cudaEventDisableTiming) == cudaSuccess);
    if (multi)
        multi = (cudaEventCreateWithFlags(&evJoin, cudaEventDisableTiming) == cudaSuccess);

    if (multi) {
        pack_kernel<<<blocks, NTHR>>>(vidx, n_cells);
        for (int b = 0; b < batches; ++b) {
            cudaMemsetAsync(out + (long long)b * n_vox, 0,
                            (size_t)n_vox * sizeof(float), 0);
            cudaEventRecord(evZ[b], 0);
        }
        for (int b0 = 0; b0 < batches; b0 += GROUP) {
            const int nb = (batches - b0 < GROUP) ? (batches - b0) : GROUP;
            cudaStreamWaitEvent(s2, evZ[b0 + nb - 1], 0);
            scatter_group_kernel<<<blocks, NTHR, 0, s2>>>(
                polar + (size_t)b0 * n_cells,
                out + (long long)b0 * n_vox,
                n_cells, n_vox, nb);
        }
        cudaEventRecord(evJoin, s2);
        cudaStreamWaitEvent(0, evJoin, 0);
    } else {
        cudaMemsetAsync(d_out, 0, (size_t)out_size * sizeof(float), 0);
        for (int b = 0; b < batches; ++b)
            scatter_fallback_kernel<<<blocks, NTHR>>>(
                polar + (size_t)b * n_cells, vidx,
                out + (long long)b * n_vox, n_cells);
    }
}

// round 9
// speedup vs baseline: 1.1271x; 1.1271x over previous
#include <cuda_runtime.h>
#include <cstdint>

// PolarToCartesianGrid: batched scatter-add into a cartesian voxel grid.
//
// R9: same fork/join pipeline as R8, but the zeroing chain uses 4 LARGE
// memset nodes (4 slabs = 131MB each) instead of 16 small ones. R5/R6/R8
// all timed ~165-170us == the 16-node memset chain (small nodes run at
// ~3.2TB/s effective vs 5.95TB/s for one big memset). Large nodes restore
// engine rate; scatter groups (proven hidden) ride under them.
//   stream 0 : 4 x memset(4 slabs), event after each.
//   stream s2: pack kernel (overlaps memset 0), then scatter-group g gated
//              on memset-group g. join at end.

#define NTHR 256
#define MAX_CELLS (1 << 21)
#define MAX_BATCHES 32
#define GROUP 4
#define MAX_GROUPS (MAX_BATCHES / GROUP)

__device__ unsigned g_packed[MAX_CELLS];   // idx[23b] | (flags[6b] << 23)

// flags: bit0 = segment head; bit{1..5} = lane+d (d=1,2,4,8,16) same index
__global__ void pack_kernel(const int* __restrict__ vidx, int n_cells)
{
    const int cell = blockIdx.x * blockDim.x + threadIdx.x;
    if (cell >= n_cells) return;
    const unsigned FULL = 0xFFFFFFFFu;
    const int lane = threadIdx.x & 31;

    const int idx = vidx[cell];
    const int prev = __shfl_up_sync(FULL, idx, 1);
    unsigned f = (lane == 0 || prev != idx) ? 1u : 0u;
    int t;
    t = __shfl_down_sync(FULL, idx, 1);  if (lane + 1  < 32 && t == idx) f |= 2u;
    t = __shfl_down_sync(FULL, idx, 2);  if (lane + 2  < 32 && t == idx) f |= 4u;
    t = __shfl_down_sync(FULL, idx, 4);  if (lane + 4  < 32 && t == idx) f |= 8u;
    t = __shfl_down_sync(FULL, idx, 8);  if (lane + 8  < 32 && t == idx) f |= 16u;
    t = __shfl_down_sync(FULL, idx, 16); if (lane + 16 < 32 && t == idx) f |= 32u;
    g_packed[cell] = (unsigned)idx | (f << 23);
}

// scatter a group of `nb` (1..4) consecutive batches
__global__ __launch_bounds__(NTHR)
void scatter_group_kernel(const float* __restrict__ polar_g,  // batch b0
                          float*       __restrict__ out_g,    // slab b0
                          int n_cells, long long n_vox, int nb)
{
    const int cell = blockIdx.x * blockDim.x + threadIdx.x;
    if (cell >= n_cells) return;               // n_cells % 256 == 0
    const unsigned FULL = 0xFFFFFFFFu;

    const unsigned p   = g_packed[cell];
    const unsigned idx = p & 0x7FFFFFu;
    const unsigned f   = p >> 23;

    // all polar loads up front (MLP 4)
    float v[GROUP];
    #pragma unroll
    for (int i = 0; i < GROUP; ++i)
        v[i] = (i < nb) ? __ldg(polar_g + (size_t)i * n_cells + cell) : 0.f;

    // interleaved segmented suffix reductions (head lane ends with run sum)
    float t[GROUP];
    #pragma unroll
    for (int d = 1; d <= 16; d <<= 1) {
        #pragma unroll
        for (int i = 0; i < GROUP; ++i) t[i] = __shfl_down_sync(FULL, v[i], d);
        const unsigned bit = (unsigned)d << 1;      // d=1->2, ..., 16->32
        if (f & bit) {
            #pragma unroll
            for (int i = 0; i < GROUP; ++i) v[i] += t[i];
        }
    }

    if (f & 1u) {
        #pragma unroll
        for (int i = 0; i < GROUP; ++i)
            if (i < nb) atomicAdd(out_g + (long long)i * n_vox + idx, v[i]);
    }
}

// fallback: R1-style serial path
__global__ void scatter_fallback_kernel(const float* __restrict__ polar_b,
                                        const int*   __restrict__ vidx,
                                        float*       __restrict__ out_b,
                                        int n_cells)
{
    const int cell = blockIdx.x * blockDim.x + threadIdx.x;
    if (cell >= n_cells) return;
    const unsigned FULL = 0xFFFFFFFFu;
    const int lane = threadIdx.x & 31;
    const int idx = vidx[cell];
    float v = __ldg(polar_b + cell);
    const unsigned peers = __match_any_sync(FULL, idx);
    const int rank = __popc(peers & ((1u << lane) - 1u));
    const unsigned s1  = __fns(peers, lane, 2);
    const unsigned s2  = __fns(peers, lane, 3);
    const unsigned s4  = __fns(peers, lane, 5);
    const unsigned s8  = __fns(peers, lane, 9);
    const unsigned s16 = __fns(peers, lane, 17);
    float t;
    t = __shfl_sync(FULL, v, s1  & 31); if (s1  < 32) v += t;
    t = __shfl_sync(FULL, v, s2  & 31); if (s2  < 32) v += t;
    t = __shfl_sync(FULL, v, s4  & 31); if (s4  < 32) v += t;
    t = __shfl_sync(FULL, v, s8  & 31); if (s8  < 32) v += t;
    t = __shfl_sync(FULL, v, s16 & 31); if (s16 < 32) v += t;
    if (rank == 0) atomicAdd(out_b + idx, v);
}

extern "C" void kernel_launch(void* const* d_in, const int* in_sizes, int n_in,
                              void* d_out, int out_size)
{
    const float* polar = (const float*)d_in[0];            // [B,1,El,R,Az] f32
    const int*   vidx  = (const int*)d_in[1];              // [El*R*Az] int32
    float*       out   = (float*)d_out;                    // [B,1,Z,Y,X] f32

    const int n_cells = in_sizes[1];                       // 1,048,576
    int batches = in_sizes[0] / n_cells;                   // 16
    if (batches > MAX_BATCHES) batches = MAX_BATCHES;
    const long long n_vox = (long long)out_size / batches; // 8,192,000

    const int blocks = (n_cells + NTHR - 1) / NTHR;
    const bool packable = (n_cells <= MAX_CELLS) && (n_vox < (1LL << 23));

    const int n_groups_launch = (batches + GROUP - 1) / GROUP;

    cudaStream_t s2 = nullptr;
    cudaEvent_t  evZ[MAX_GROUPS] = {};
    cudaEvent_t  evJoin = nullptr;
    bool multi = packable &&
                 (cudaStreamCreateWithFlags(&s2, cudaStreamNonBlocking) == cudaSuccess);
    for (int i = 0; i < n_groups_launch && multi; ++i)
        multi = (cudaEventCreateWithFlags(&evZ[i], cudaEventDisableTiming) == cudaSuccess);
    if (multi)
        multi = (cudaEventCreateWithFlags(&evJoin, cudaEventDisableTiming) == cudaSuccess);

    if (multi) {
        // stream 0: LARGE memset nodes (GROUP slabs each) at engine rate
        for (int g = 0; g < n_groups_launch; ++g) {
            const int b0 = g * GROUP;
            const int nb = (batches - b0 < GROUP) ? (batches - b0) : GROUP;
            cudaMemsetAsync(out + (long long)b0 * n_vox, 0,
                            (size_t)nb * (size_t)n_vox * sizeof(float), 0);
            cudaEventRecord(evZ[g], 0);
        }
        // s2: pack overlaps memset 0; scatter-group g gated on memset g
        pack_kernel<<<blocks, NTHR, 0, s2>>>(vidx, n_cells);
        for (int g = 0; g < n_groups_launch; ++g) {
            const int b0 = g * GROUP;
            const int nb = (batches - b0 < GROUP) ? (batches - b0) : GROUP;
            cudaStreamWaitEvent(s2, evZ[g], 0);
            scatter_group_kernel<<<blocks, NTHR, 0, s2>>>(
                polar + (size_t)b0 * n_cells,
                out + (long long)b0 * n_vox,
                n_cells, n_vox, nb);
        }
        cudaEventRecord(evJoin, s2);
        cudaStreamWaitEvent(0, evJoin, 0);
    } else {
        cudaMemsetAsync(d_out, 0, (size_t)out_size * sizeof(float), 0);
        for (int b = 0; b < batches; ++b)
            scatter_fallback_kernel<<<blocks, NTHR>>>(
                polar + (size_t)b * n_cells, vidx,
                out + (long long)b * n_vox, n_cells);
    }
}